// round 11
// baseline (speedup 1.0000x reference)
#include <cuda_runtime.h>
#include <cstdint>

// Inputs (metadata order):
//   d_in[0] state           float32 [B, A, N, 3]
//   d_in[1] nodes_coords    float32 [P, 2]
//   d_in[2] adj             float32 [P, N]
//   d_in[3] node_last_visit int32   [B, A]
//   d_in[4] patrol_index    int32   [P]
// Output: float32 [B, A, N, 6]
//
// Two-kernel pipeline:
//   K1 (tiny): per row, resolve the dependent chain nlv->pidx->coords and
//       pack (zx, zy, idx) into one float4 in __device__ scratch (L2-resident).
//   K2 (main): R10 structure — per-warp independent gather->STS.128->bulk-store
//       pipelines, but the row-constant chain is now ONE LDG.128 L2 hit.

#define MAX_ROWS 32768
__device__ float4 g_rowconst[MAX_ROWS];   // static scratch (no allocation)

__global__ void precompute_rowconst(const float* __restrict__ coords,
                                    const int*   __restrict__ nlv,
                                    const int*   __restrict__ pidx,
                                    int BA) {
    const int i = blockIdx.x * blockDim.x + threadIdx.x;
    if (i < BA) {
        const int v   = __ldg(nlv + i);
        const int idx = __ldg(pidx + v);
        const float zx = __ldg(coords + 2 * v);
        const float zy = __ldg(coords + 2 * v + 1);
        g_rowconst[i] = make_float4(zx, zy, __int_as_float(idx), 0.0f);
    }
}

__global__ __launch_bounds__(128)
void policy_gather_kernel(const float* __restrict__ state,
                          const float* __restrict__ coords,
                          const float* __restrict__ adj,
                          const int*   __restrict__ nlv,
                          const int*   __restrict__ pidx,
                          float* __restrict__ out,
                          int N, int useRC) {
    extern __shared__ __align__(16) float s_row[];   // N*6 floats, output-row image

    const int row  = blockIdx.x;
    const int t    = threadIdx.x;
    const int warp = t >> 5;
    const int lane = t & 31;

    // Row constants: single L2-hit LDG.128 when precomputed, else the chain.
    float zx, zy;
    int   idx;
    if (useRC) {
        const float4 c = __ldg(&g_rowconst[row]);
        zx  = c.x;
        zy  = c.y;
        idx = __float_as_int(c.z);
    } else {
        const int v = __ldg(nlv + row);
        idx = __ldg(pidx + v);
        zx  = __ldg(coords + 2 * v);
        zy  = __ldg(coords + 2 * v + 1);
    }

    const float* __restrict__ st = state + (size_t)row * N * 3;   // 8B aligned
    const float* __restrict__ ar = adj   + (size_t)idx * N;       // 8B aligned
    float* __restrict__ orow     = out   + (size_t)row * N * 6;   // 16B aligned

    const bool okA   = (((((uintptr_t)st) | ((uintptr_t)ar)) & 7) == 0);
    const bool okTMA = ((((uintptr_t)orow) & 0xF) == 0);

    if (okA && okTMA) {
        const int pairs = N >> 1;

        // Each warp: independent gather -> STS.128 -> per-warp bulk store.
        for (int start = warp * 32; start < pairs; start += 128) {
            const int cnt = min(32, pairs - start);
            const int p   = start + lane;

            if (lane < cnt) {
                const float2 s01 = __ldcs(reinterpret_cast<const float2*>(st + 6 * p));
                const float2 s23 = __ldcs(reinterpret_cast<const float2*>(st + 6 * p + 2));
                const float2 s45 = __ldcs(reinterpret_cast<const float2*>(st + 6 * p + 4));
                const float2 aa  = __ldg (reinterpret_cast<const float2*>(ar + 2 * p));

                float4* d = reinterpret_cast<float4*>(s_row + 12 * p);  // 16B aligned
                d[0] = make_float4(s01.x, s01.y, s23.x, zx);
                d[1] = make_float4(zy,    aa.x,  s23.y, s45.x);
                d[2] = make_float4(s45.y, zx,    zy,    aa.y);
            }
            __syncwarp();
            asm volatile("fence.proxy.async.shared::cta;" ::: "memory");

            if (lane == 0) {
                const unsigned bytes = (unsigned)(cnt * 12 * sizeof(float));  // mult of 48
                float* gdst = orow + (size_t)start * 12;
                uint32_t saddr;
                asm("{ .reg .u64 tmp; cvta.to.shared.u64 tmp, %1; cvt.u32.u64 %0, tmp; }"
                    : "=r"(saddr) : "l"(s_row + 12 * start));
                asm volatile(
                    "cp.async.bulk.global.shared::cta.bulk_group [%0], [%1], %2;"
                    :: "l"(gdst), "r"(saddr), "r"(bytes) : "memory");
                asm volatile("cp.async.bulk.commit_group;" ::: "memory");
            }
        }

        // Odd-N tail node.
        if ((N & 1) && t == 0) {
            const int n = N - 1;
            float* d = orow + 6 * n;
            __stcs(d + 0, st[3 * n + 0]);
            __stcs(d + 1, st[3 * n + 1]);
            __stcs(d + 2, st[3 * n + 2]);
            __stcs(d + 3, zx);
            __stcs(d + 4, zy);
            __stcs(d + 5, ar[n]);
        }

        // Exit gate: smem READ completion only.
        if (lane == 0) {
            asm volatile("cp.async.bulk.wait_group.read 0;" ::: "memory");
        }
    } else {
        // Fallback: staged scalar copy with full-block sync.
        for (int n = t; n < N; n += blockDim.x) {
            float* d = s_row + 6 * n;
            d[0] = st[3 * n + 0];
            d[1] = st[3 * n + 1];
            d[2] = st[3 * n + 2];
            d[3] = zx;
            d[4] = zy;
            d[5] = ar[n];
        }
        __syncthreads();
        const int total = N * 6;
        for (int j = t; j < total; j += blockDim.x) {
            __stcs(orow + j, s_row[j]);
        }
    }
}

extern "C" void kernel_launch(void* const* d_in, const int* in_sizes, int n_in,
                              void* d_out, int out_size) {
    const float* state  = (const float*)d_in[0];
    const float* coords = (const float*)d_in[1];
    const float* adj    = (const float*)d_in[2];
    const int*   nlv    = (const int*)d_in[3];
    const int*   pidx   = (const int*)d_in[4];
    float*       out    = (float*)d_out;

    const int BA = in_sizes[3];            // B * A rows
    const int P  = in_sizes[4];            // patrol nodes
    const int N  = in_sizes[2] / P;        // graph size (adj is [P, N])

    const int useRC = (BA <= MAX_ROWS) ? 1 : 0;
    if (useRC) {
        precompute_rowconst<<<(BA + 255) / 256, 256>>>(coords, nlv, pidx, BA);
    }

    const size_t smem = (size_t)N * 6 * sizeof(float);
    policy_gather_kernel<<<BA, 128, smem>>>(state, coords, adj, nlv, pidx, out, N, useRC);
}